// round 2
// baseline (speedup 1.0000x reference)
#include <cuda_runtime.h>
#include <cuda_bf16.h>

// AMMaskedLinear: B=64, IN=1024, OUT=1024, D=32.
//
// out[b,k] = om[b,k] * (cscale_b[k] * y[b,k] + cbias_b[k])
//   om[b,k]  = (r_high[k] appears in hidden_rank[b,:])
//   y[b,k]   = sum_i [ ml[b,i] in 1..mh[b,k] ] * direction[k,i] * x[b,i]
//   ml[b,i]  = r_low[i]  if r_low[i]  appears in hidden_rank[b,:] else 0
//   mh[b,k]  = r_high[k] if om[b,k] else 0
//
// hidden_rank values are in [0,32] -> a per-batch 33-bit presence bitmap
// replaces both O(1024^2) "any(==)" reductions. scale/bias reduce exactly to
// cscale_b / cbias_b (zeros @ W.T == 0). The matvec y is observable only when
// cscale_b[k] != 0, so it is gated on that (data-dependent, deterministic,
// graph-capture-safe; with the dataset seed cscale_b == 0 so it never runs).

#define B_   64
#define IN_  1024
#define OUT_ 1024

__global__ __launch_bounds__(1024, 1)
void am_masked_linear_kernel(const float* __restrict__ x,
                             const int*   __restrict__ hidden_rank,
                             const int*   __restrict__ r_low,
                             const int*   __restrict__ r_high,
                             const float* __restrict__ direction,
                             const float* __restrict__ cscale_b,
                             const float* __restrict__ cbias_b,
                             float*       __restrict__ out) {
    __shared__ unsigned int s_lo, s_hi;

    const int b   = blockIdx.x;
    const int tid = threadIdx.x;

    if (tid == 0) { s_lo = 0u; s_hi = 0u; }
    __syncthreads();

    // Build 33-bit presence bitmap of hidden_rank[b, :] (values 0..32).
    {
        const int v = hidden_rank[b * IN_ + tid];
        unsigned int lo = (v < 32) ? (1u << v) : 0u;
        unsigned int hi = (v >= 32) ? 1u : 0u;
        lo = __reduce_or_sync(0xffffffffu, lo);
        hi = __reduce_or_sync(0xffffffffu, hi);
        if ((tid & 31) == 0) {
            atomicOr(&s_lo, lo);
            atomicOr(&s_hi, hi);
        }
    }
    __syncthreads();

    const unsigned long long p =
        ((unsigned long long)s_hi << 32) | (unsigned long long)s_lo;

    const int k  = tid;
    const int rh = r_high[k];                       // 0..32
    const bool om = (p >> rh) & 1ull;               // out_mask[b,k]

    float result = 0.0f;
    if (om) {
        const float sc = cscale_b[k];
        float y = 0.0f;
        // y is observable only if sc != 0; mh = rh (om true), terms need ml>=1.
        if (sc != 0.0f && rh > 0) {
            // allowed values v: 1 <= v <= rh AND v present in hidden_rank[b,:]
            const unsigned long long allowed = p & ((2ull << rh) - 2ull);
            const float* __restrict__ drow = direction + (size_t)k * IN_;
            const float* __restrict__ xrow = x + (size_t)b * IN_;
            #pragma unroll 4
            for (int i = 0; i < IN_; ++i) {
                if ((allowed >> r_low[i]) & 1ull)
                    y = fmaf(drow[i], xrow[i], y);
            }
        }
        result = fmaf(sc, y, cbias_b[k]);
    }
    out[b * OUT_ + k] = result;
}

extern "C" void kernel_launch(void* const* d_in, const int* in_sizes, int n_in,
                              void* d_out, int out_size) {
    // metadata order: x, mask, pre_mask, hidden_rank, r_low, r_high,
    //                 direction, cscale_w, cscale_b, cbias_w, cbias_b
    const float* x           = (const float*)d_in[0];
    const int*   hidden_rank = (const int*)  d_in[3];
    const int*   r_low       = (const int*)  d_in[4];
    const int*   r_high      = (const int*)  d_in[5];
    const float* direction   = (const float*)d_in[6];
    const float* cscale_b    = (const float*)d_in[8];
    const float* cbias_b     = (const float*)d_in[10];
    float* out = (float*)d_out;

    am_masked_linear_kernel<<<B_, OUT_>>>(x, hidden_rank, r_low, r_high,
                                          direction, cscale_b, cbias_b, out);
}